// round 1
// baseline (speedup 1.0000x reference)
#include <cuda_runtime.h>
#include <cuda_fp16.h>

// Problem constants (fixed by the dataset)
#define B_TOTAL   32768
#define N_IN      128
#define NLAYERS   8
#define WID       256
#define KK        16
#define T         32          // batch rows per block (lane = row)
#define NTHREADS  1024
#define NWARPS    32
#define VALS_COLS 1920        // 128 + 7*256 ; layer-7 output never re-gathered

// SMEM plan (dynamic):
//   s_vals : __half [VALS_COLS][T]            = 122,880 B  (activation history, transposed)
//   s_aux  : float  [32*257]                  =  32,896 B  (input staging [32][129] / output staging [32][257])
#define SMEM_BYTES (VALS_COLS * T * 2 + 32 * 257 * 4)

extern __shared__ unsigned char smem_raw[];

__global__ __launch_bounds__(NTHREADS, 1)
void ffn_edge_kernel(const float* __restrict__ inputs,    // [B, 128]
                     const float* __restrict__ weights,   // [L, W, K]
                     const float* __restrict__ biases,    // [L, W]
                     const int*   __restrict__ edge_idx,  // [L, W, K]
                     float*       __restrict__ out)       // [B, W]
{
    __half* s_vals = (__half*)smem_raw;
    float*  s_aux  = (float*)(smem_raw + VALS_COLS * T * sizeof(__half));

    const int tid  = threadIdx.x;
    const int lane = tid & 31;
    const int wid  = tid >> 5;
    const int row0 = blockIdx.x * T;

    // ---- Stage input tile coalesced into s_aux as [T][129] (pad kills bank conflicts) ----
    {
        const float4* in4 = (const float4*)(inputs + (size_t)row0 * N_IN);
        #pragma unroll 1
        for (int i = tid; i < T * (N_IN / 4); i += NTHREADS) {
            int r  = i >> 5;      // 32 float4 per row
            int c4 = i & 31;
            float4 v = in4[i];
            float* dst = s_aux + r * 129 + c4 * 4;
            dst[0] = v.x; dst[1] = v.y; dst[2] = v.z; dst[3] = v.w;
        }
    }
    __syncthreads();
    // ---- Transpose-convert input into s_vals [col][row] as fp16 ----
    #pragma unroll 1
    for (int i = tid; i < T * N_IN; i += NTHREADS) {
        int col = i >> 5;         // 0..127
        int r   = i & 31;
        s_vals[col * T + r] = __float2half(s_aux[r * 129 + col]);
    }
    __syncthreads();

    // ---- 8 layers ----
    int ncols = N_IN;
    #pragma unroll 1
    for (int l = 0; l < NLAYERS; ++l) {
        const int4*   idx4 = (const int4*)  (edge_idx + (size_t)l * WID * KK);
        const float4* wt4  = (const float4*)(weights  + (size_t)l * WID * KK);
        const float*  bptr = biases + l * WID;
        const bool last = (l == NLAYERS - 1);

        #pragma unroll 1
        for (int w = wid; w < WID; w += NWARPS) {
            float a0 = __ldg(bptr + w);
            float a1 = 0.0f;
            #pragma unroll
            for (int g = 0; g < 4; ++g) {
                int4   iv = idx4[w * 4 + g];
                float4 wv = wt4 [w * 4 + g];
                a0 += __half2float(s_vals[iv.x * T + lane]) * wv.x;
                a1 += __half2float(s_vals[iv.y * T + lane]) * wv.y;
                a0 += __half2float(s_vals[iv.z * T + lane]) * wv.z;
                a1 += __half2float(s_vals[iv.w * T + lane]) * wv.w;
            }
            float pre = a0 + a1;
            float sig = __frcp_rn(1.0f + __expf(-pre));
            if (!last) {
                s_vals[(ncols + w) * T + lane] = __float2half(sig); // conflict-free (2B, lanes consecutive)
            } else {
                s_aux[lane * 257 + w] = sig;  // stride-257 pad -> conflict-free across lanes
            }
        }
        ncols += WID;
        __syncthreads();
    }

    // ---- Coalesced fp32 output: out[row0+r][c] = s_aux[r*257+c] ----
    float* og = out + (size_t)row0 * WID;
    #pragma unroll 1
    for (int i = tid; i < T * WID; i += NTHREADS) {
        int r = i >> 8;
        int c = i & 255;
        og[i] = s_aux[r * 257 + c];
    }
}

extern "C" void kernel_launch(void* const* d_in, const int* in_sizes, int n_in,
                              void* d_out, int out_size)
{
    (void)in_sizes; (void)n_in; (void)out_size;
    const float* inputs   = (const float*)d_in[0];
    const float* weights  = (const float*)d_in[1];
    const float* biases   = (const float*)d_in[2];
    const int*   edge_idx = (const int*)  d_in[3];
    float*       out      = (float*)d_out;

    // Opt into >48KB dynamic SMEM (idempotent; not a stream op, capture-safe)
    cudaFuncSetAttribute(ffn_edge_kernel,
                         cudaFuncAttributeMaxDynamicSharedMemorySize, SMEM_BYTES);

    dim3 grid(B_TOTAL / T);   // 1024 blocks, exact
    dim3 block(NTHREADS);
    ffn_edge_kernel<<<grid, block, SMEM_BYTES>>>(inputs, weights, biases, edge_idx, out);
}

// round 2
// speedup vs baseline: 1.3535x; 1.3535x over previous
#include <cuda_runtime.h>
#include <cuda_fp16.h>

// Problem constants (fixed by the dataset)
#define B_TOTAL   32768
#define N_IN      128
#define NLAYERS   8
#define WID       256
#define KK        16
#define T         64          // batch rows per block; lane carries a row PAIR (half2)
#define NTHREADS  1024
#define NWARPS    32
#define NBLOCKS   (B_TOTAL / T)          // 512
#define SMEM_COLS 1664        // cols resident in SMEM: input(128) + layers 0..5 (6*256)
// layer-6 output (cols 1664..1919) lives in global scratch, gathered only by layer 7

// s_vals: __half2 [SMEM_COLS][32]  (col-major history, row pairs packed) = 212,992 B
#define SMEM_BYTES (SMEM_COLS * T * 2)

// Global scratch for layer-6 outputs: [block][w][32 row-pairs] = 16 MB (static, allowed)
__device__ __half2 g6_scratch[(size_t)NBLOCKS * WID * (T / 2)];

extern __shared__ unsigned char smem_raw[];

__device__ __forceinline__ void mac2(float2& acc, __half2 h, float wt) {
    float2 v = __half22float2(h);
    acc.x = fmaf(v.x, wt, acc.x);
    acc.y = fmaf(v.y, wt, acc.y);
}

__device__ __forceinline__ float2 sigmoid2(float2 pre) {
    float2 s;
    s.x = __fdividef(1.0f, 1.0f + __expf(-pre.x));
    s.y = __fdividef(1.0f, 1.0f + __expf(-pre.y));
    return s;
}

// dot over 16 edges, all cols guaranteed < SMEM_COLS (layers 0..6)
__device__ __forceinline__ float2 pre_smem(const __half2* __restrict__ s_h2,
                                           const int4* __restrict__ idx4,
                                           const float4* __restrict__ wt4,
                                           float bias, int w, int lane) {
    float2 a0 = make_float2(bias, 0.0f), a1 = make_float2(0.0f, bias);
    #pragma unroll
    for (int g = 0; g < 4; ++g) {
        int4   iv = __ldg(idx4 + w * 4 + g);
        float4 wv = __ldg(wt4  + w * 4 + g);
        mac2(a0, s_h2[iv.x * 32 + lane], wv.x);
        mac2(a1, s_h2[iv.y * 32 + lane], wv.y);
        mac2(a0, s_h2[iv.z * 32 + lane], wv.z);
        mac2(a1, s_h2[iv.w * 32 + lane], wv.w);
    }
    return make_float2(a0.x + a1.x, a0.y + a1.y);
}

// layer 7: cols may be >= SMEM_COLS -> branchless pointer select (generic LD)
__device__ __forceinline__ float2 pre_mixed(const __half2* __restrict__ s_h2,
                                            const __half2* __restrict__ gblk,
                                            const int4* __restrict__ idx4,
                                            const float4* __restrict__ wt4,
                                            float bias, int w, int lane) {
    float2 a0 = make_float2(bias, 0.0f), a1 = make_float2(0.0f, bias);
    #pragma unroll
    for (int g = 0; g < 4; ++g) {
        int4   iv = __ldg(idx4 + w * 4 + g);
        float4 wv = __ldg(wt4  + w * 4 + g);
        const __half2* px = (iv.x < SMEM_COLS) ? (s_h2 + iv.x * 32) : (gblk + (iv.x - SMEM_COLS) * 32);
        const __half2* py = (iv.y < SMEM_COLS) ? (s_h2 + iv.y * 32) : (gblk + (iv.y - SMEM_COLS) * 32);
        const __half2* pz = (iv.z < SMEM_COLS) ? (s_h2 + iv.z * 32) : (gblk + (iv.z - SMEM_COLS) * 32);
        const __half2* pw = (iv.w < SMEM_COLS) ? (s_h2 + iv.w * 32) : (gblk + (iv.w - SMEM_COLS) * 32);
        mac2(a0, px[lane], wv.x);
        mac2(a1, py[lane], wv.y);
        mac2(a0, pz[lane], wv.z);
        mac2(a1, pw[lane], wv.w);
    }
    return make_float2(a0.x + a1.x, a0.y + a1.y);
}

__global__ __launch_bounds__(NTHREADS, 1)
void ffn_edge_kernel(const float* __restrict__ inputs,    // [B, 128]
                     const float* __restrict__ weights,   // [L, W, K]
                     const float* __restrict__ biases,    // [L, W]
                     const int*   __restrict__ edge_idx,  // [L, W, K]
                     float*       __restrict__ out)       // [B, W]
{
    __half2* s_h2 = (__half2*)smem_raw;

    const int tid  = threadIdx.x;
    const int lane = tid & 31;
    const int wid  = tid >> 5;
    const int row0 = blockIdx.x * T;

    __half2* gblk = g6_scratch + (size_t)blockIdx.x * (WID * (T / 2));

    // ---- Stage input [64][128] fp32 coalesced into a pad-132 buffer.
    // Staging overlays bytes [16384, 50160) of s_vals (cols 128..391, not yet written).
    float* s_stage = (float*)(smem_raw + 16384);
    {
        const float4* in4 = (const float4*)(inputs + (size_t)row0 * N_IN);
        #pragma unroll 1
        for (int i = tid; i < T * (N_IN / 4); i += NTHREADS) {
            int r  = i >> 5;            // 32 float4 per row
            int c4 = i & 31;
            float4 v = in4[i];
            float* dst = s_stage + r * 132 + c4 * 4;
            dst[0] = v.x; dst[1] = v.y; dst[2] = v.z; dst[3] = v.w;
        }
    }
    __syncthreads();
    // ---- Transpose-convert input into s_h2[col][pair]: lo = row 2p, hi = row 2p+1
    #pragma unroll 1
    for (int i = tid; i < N_IN * 32; i += NTHREADS) {
        int col = i >> 5;
        int p   = i & 31;
        float lo = s_stage[(2 * p)     * 132 + col];
        float hi = s_stage[(2 * p + 1) * 132 + col];
        s_h2[col * 32 + p] = __floats2half2_rn(lo, hi);
    }
    __syncthreads();

    // ---- Layers 0..5: outputs to SMEM ----
    int ncols = N_IN;
    #pragma unroll 1
    for (int l = 0; l < 6; ++l) {
        const int4*   idx4 = (const int4*)  (edge_idx + (size_t)l * WID * KK);
        const float4* wt4  = (const float4*)(weights  + (size_t)l * WID * KK);
        const float*  bptr = biases + l * WID;
        #pragma unroll 1
        for (int w = wid; w < WID; w += NWARPS) {
            float2 pre = pre_smem(s_h2, idx4, wt4, __ldg(bptr + w), w, lane);
            float2 sg  = sigmoid2(pre);
            s_h2[(ncols + w) * 32 + lane] = __floats2half2_rn(sg.x, sg.y);
        }
        ncols += WID;
        __syncthreads();
    }

    // ---- Layer 6: output to global scratch (transposed, coalesced 128B stores) ----
    {
        const int4*   idx4 = (const int4*)  (edge_idx + (size_t)6 * WID * KK);
        const float4* wt4  = (const float4*)(weights  + (size_t)6 * WID * KK);
        const float*  bptr = biases + 6 * WID;
        #pragma unroll 1
        for (int w = wid; w < WID; w += NWARPS) {
            float2 pre = pre_smem(s_h2, idx4, wt4, __ldg(bptr + w), w, lane);
            float2 sg  = sigmoid2(pre);
            gblk[w * 32 + lane] = __floats2half2_rn(sg.x, sg.y);
        }
        __syncthreads();   // orders gblk stores before layer-7 loads (same block)
    }

    // ---- Layer 7: gathers from SMEM or scratch; fp32 result straight to GMEM ----
    {
        const int4*   idx4 = (const int4*)  (edge_idx + (size_t)7 * WID * KK);
        const float4* wt4  = (const float4*)(weights  + (size_t)7 * WID * KK);
        const float*  bptr = biases + 7 * WID;
        float* og = out + ((size_t)row0 + 2 * lane) * WID;
        #pragma unroll 1
        for (int w = wid; w < WID; w += NWARPS) {
            float2 pre = pre_mixed(s_h2, gblk, idx4, wt4, __ldg(bptr + w), w, lane);
            float2 sg  = sigmoid2(pre);
            og[w]       = sg.x;   // row 2*lane
            og[w + WID] = sg.y;   // row 2*lane + 1
        }
    }
}

extern "C" void kernel_launch(void* const* d_in, const int* in_sizes, int n_in,
                              void* d_out, int out_size)
{
    (void)in_sizes; (void)n_in; (void)out_size;
    const float* inputs   = (const float*)d_in[0];
    const float* weights  = (const float*)d_in[1];
    const float* biases   = (const float*)d_in[2];
    const int*   edge_idx = (const int*)  d_in[3];
    float*       out      = (float*)d_out;

    cudaFuncSetAttribute(ffn_edge_kernel,
                         cudaFuncAttributeMaxDynamicSharedMemorySize, SMEM_BYTES);

    dim3 grid(NBLOCKS);        // 512 blocks of 64 rows
    dim3 block(NTHREADS);
    ffn_edge_kernel<<<grid, block, SMEM_BYTES>>>(inputs, weights, biases, edge_idx, out);
}

// round 4
// speedup vs baseline: 1.5793x; 1.1669x over previous
#include <cuda_runtime.h>
#include <cuda_fp16.h>
#include <cstdint>

// Problem constants (fixed by the dataset)
#define B_TOTAL   32768
#define N_IN      128
#define NLAYERS   8
#define WID       256
#define KK        16
#define T         64          // batch rows per block; lane carries a row PAIR (half2)
#define NTHREADS  1024
#define NWARPS    32
#define NBLOCKS   (B_TOTAL / T)          // 512
#define SPLIT     1536        // cols < SPLIT live in SMEM; cols >= SPLIT in global scratch
#define NCOLS_ALL 1920        // 128 + 7*256 (layer-7 out never re-gathered)

// SMEM layout (dynamic, 230,400 B total):
//   [0      , 196608) s_hist  : __half2 [1536][32]   (history, transposed, row pairs)
//   [196608 , 212992) s_tidx  : int     [256*16]     (current layer edge indices)
//   [212992 , 229376) s_twt   : float   [256*16]     (current layer weights)
//   [229376 , 230400) s_tbias : float   [256]        (current layer biases)
#define OFF_TIDX  196608
#define OFF_TWT   212992
#define OFF_TBIAS 229376
#define SMEM_BYTES 230400

// Global scratch for evicted history cols [1536, 1920): [block][col'][32 pairs]
#define SC_COLS (NCOLS_ALL - SPLIT)      // 384
__device__ __half2 g_scratch[(size_t)NBLOCKS * SC_COLS * (T / 2)];

extern __shared__ unsigned char smem_raw[];

__device__ __forceinline__ void cp16(unsigned int saddr, const void* gptr) {
    asm volatile("cp.async.cg.shared.global [%0], [%1], 16;\n"
                 :: "r"(saddr), "l"(gptr));
}

__device__ __forceinline__ void mac2(float2& acc, __half2 h, float wt) {
    float2 v = __half22float2(h);
    acc.x = fmaf(v.x, wt, acc.x);
    acc.y = fmaf(v.y, wt, acc.y);
}

__device__ __forceinline__ float2 sigmoid2(float2 pre) {
    float2 s;
    s.x = __fdividef(1.0f, 1.0f + __expf(-pre.x));
    s.y = __fdividef(1.0f, 1.0f + __expf(-pre.y));
    return s;
}

// 16-edge dot, all cols < SPLIT guaranteed (layers 0..5); tables read from SMEM
__device__ __forceinline__ float2 pre_smem(const __half2* __restrict__ s_h2,
                                           const int4* __restrict__ si4,
                                           const float4* __restrict__ sw4,
                                           float bias, int w, int lane) {
    float2 a0 = make_float2(bias, 0.0f), a1 = make_float2(0.0f, bias);
    #pragma unroll
    for (int g = 0; g < 4; ++g) {
        int4   iv = si4[w * 4 + g];
        float4 wv = sw4[w * 4 + g];
        mac2(a0, s_h2[iv.x * 32 + lane], wv.x);
        mac2(a1, s_h2[iv.y * 32 + lane], wv.y);
        mac2(a0, s_h2[iv.z * 32 + lane], wv.z);
        mac2(a1, s_h2[iv.w * 32 + lane], wv.w);
    }
    return make_float2(a0.x + a1.x, a0.y + a1.y);
}

// layers 6,7: cols may be >= SPLIT -> branchless pointer select (generic LD)
__device__ __forceinline__ float2 pre_mixed(const __half2* __restrict__ s_h2,
                                            const __half2* __restrict__ gblk,
                                            const int4* __restrict__ si4,
                                            const float4* __restrict__ sw4,
                                            float bias, int w, int lane) {
    float2 a0 = make_float2(bias, 0.0f), a1 = make_float2(0.0f, bias);
    #pragma unroll
    for (int g = 0; g < 4; ++g) {
        int4   iv = si4[w * 4 + g];
        float4 wv = sw4[w * 4 + g];
        const __half2* px = (iv.x < SPLIT) ? (s_h2 + iv.x * 32) : (gblk + (iv.x - SPLIT) * 32);
        const __half2* py = (iv.y < SPLIT) ? (s_h2 + iv.y * 32) : (gblk + (iv.y - SPLIT) * 32);
        const __half2* pz = (iv.z < SPLIT) ? (s_h2 + iv.z * 32) : (gblk + (iv.z - SPLIT) * 32);
        const __half2* pw = (iv.w < SPLIT) ? (s_h2 + iv.w * 32) : (gblk + (iv.w - SPLIT) * 32);
        mac2(a0, px[lane], wv.x);
        mac2(a1, py[lane], wv.y);
        mac2(a0, pz[lane], wv.z);
        mac2(a1, pw[lane], wv.w);
    }
    return make_float2(a0.x + a1.x, a0.y + a1.y);
}

__global__ __launch_bounds__(NTHREADS, 1)
void ffn_edge_kernel(const float* __restrict__ inputs,    // [B, 128]
                     const float* __restrict__ weights,   // [L, W, K]
                     const float* __restrict__ biases,    // [L, W]
                     const int*   __restrict__ edge_idx,  // [L, W, K]
                     float*       __restrict__ out)       // [B, W]
{
    __half2* s_h2   = (__half2*)smem_raw;
    const int4*   si4 = (const int4*)  (smem_raw + OFF_TIDX);
    const float4* sw4 = (const float4*)(smem_raw + OFF_TWT);
    const float*  sb  = (const float*) (smem_raw + OFF_TBIAS);

    unsigned int s_base = (unsigned int)__cvta_generic_to_shared(smem_raw);

    const int tid  = threadIdx.x;
    const int lane = tid & 31;
    const int wid  = tid >> 5;
    const int row0 = blockIdx.x * T;

    __half2* gblk = g_scratch + (size_t)blockIdx.x * (SC_COLS * (T / 2));

    // ---- Kick off layer-0 table prefetch (overlaps input staging) ----
    {
        const char* gi = (const char*)(edge_idx);
        const char* gw = (const char*)(weights);
        cp16(s_base + OFF_TIDX + tid * 16, gi + tid * 16);
        cp16(s_base + OFF_TWT  + tid * 16, gw + tid * 16);
        if (tid < 64) cp16(s_base + OFF_TBIAS + tid * 16, (const char*)biases + tid * 16);
        asm volatile("cp.async.commit_group;\n");
    }

    // ---- Stage input [64][128] fp32 coalesced into pad-132 buffer.
    // Overlays hist bytes [16384, 50176) = cols 128..391 (not yet written).
    float* s_stage = (float*)(smem_raw + 16384);
    {
        const float4* in4 = (const float4*)(inputs + (size_t)row0 * N_IN);
        #pragma unroll 1
        for (int i = tid; i < T * (N_IN / 4); i += NTHREADS) {
            int r  = i >> 5;            // 32 float4 per row
            int c4 = i & 31;
            float4 v = in4[i];
            float* dst = s_stage + r * 132 + c4 * 4;
            dst[0] = v.x; dst[1] = v.y; dst[2] = v.z; dst[3] = v.w;
        }
    }
    __syncthreads();
    // ---- Transpose-convert input into s_h2[col][pair]: lo = row 2p, hi = row 2p+1
    #pragma unroll 1
    for (int i = tid; i < N_IN * 32; i += NTHREADS) {
        int col = i >> 5;
        int p   = i & 31;
        float lo = s_stage[(2 * p)     * 132 + col];
        float hi = s_stage[(2 * p + 1) * 132 + col];
        s_h2[col * 32 + p] = __floats2half2_rn(lo, hi);
    }

    // ---- 8 layers; tables single-buffered in SMEM ----
    int ncols = N_IN;
    #pragma unroll 1
    for (int l = 0; l < NLAYERS; ++l) {
        asm volatile("cp.async.wait_group 0;\n");
        __syncthreads();   // tables visible + (l==0: input transposed) + hist stable

        if (l < 6) {
            // pure-SMEM gathers (cols < 1408 < SPLIT)
            #pragma unroll 1
            for (int w = wid; w < WID; w += NWARPS) {
                float2 pre = pre_smem(s_h2, si4, sw4, sb[w], w, lane);
                float2 sg  = sigmoid2(pre);
                __half2 h  = __floats2half2_rn(sg.x, sg.y);
                int col = ncols + w;
                if (col < SPLIT) s_h2[col * 32 + lane] = h;
                else             gblk[(col - SPLIT) * 32 + lane] = h;
            }
        } else if (l == 6) {
            // mixed gathers; output (cols 1664..1919) all to scratch
            #pragma unroll 1
            for (int w = wid; w < WID; w += NWARPS) {
                float2 pre = pre_mixed(s_h2, gblk, si4, sw4, sb[w], w, lane);
                float2 sg  = sigmoid2(pre);
                gblk[(ncols + w - SPLIT) * 32 + lane] = __floats2half2_rn(sg.x, sg.y);
            }
        } else {
            // layer 7: mixed gathers; fp32 result straight to GMEM
            float* og = out + ((size_t)row0 + 2 * lane) * WID;
            #pragma unroll 1
            for (int w = wid; w < WID; w += NWARPS) {
                float2 pre = pre_mixed(s_h2, gblk, si4, sw4, sb[w], w, lane);
                float2 sg  = sigmoid2(pre);
                og[w]       = sg.x;   // row 2*lane
                og[w + WID] = sg.y;   // row 2*lane + 1
            }
        }
        ncols += WID;

        if (l < NLAYERS - 1) {
            __syncthreads();   // everyone done reading this layer's tables + hist settled
            const char* gi = (const char*)(edge_idx + (size_t)(l + 1) * WID * KK);
            const char* gw = (const char*)(weights  + (size_t)(l + 1) * WID * KK);
            cp16(s_base + OFF_TIDX + tid * 16, gi + tid * 16);
            cp16(s_base + OFF_TWT  + tid * 16, gw + tid * 16);
            if (tid < 64)
                cp16(s_base + OFF_TBIAS + tid * 16,
                     (const char*)(biases + (size_t)(l + 1) * WID) + tid * 16);
            asm volatile("cp.async.commit_group;\n");
        }
    }
}

extern "C" void kernel_launch(void* const* d_in, const int* in_sizes, int n_in,
                              void* d_out, int out_size)
{
    (void)in_sizes; (void)n_in; (void)out_size;
    const float* inputs   = (const float*)d_in[0];
    const float* weights  = (const float*)d_in[1];
    const float* biases   = (const float*)d_in[2];
    const int*   edge_idx = (const int*)  d_in[3];
    float*       out      = (float*)d_out;

    cudaFuncSetAttribute(ffn_edge_kernel,
                         cudaFuncAttributeMaxDynamicSharedMemorySize, SMEM_BYTES);

    dim3 grid(NBLOCKS);        // 512 blocks of 64 rows
    dim3 block(NTHREADS);
    ffn_edge_kernel<<<grid, block, SMEM_BYTES>>>(inputs, weights, biases, edge_idx, out);
}

// round 6
// speedup vs baseline: 1.8616x; 1.1787x over previous
#include <cuda_runtime.h>
#include <cuda_fp16.h>
#include <cstdint>

// Problem constants (fixed by the dataset)
#define B_TOTAL   32768
#define N_IN      128
#define NLAYERS   8
#define WID       256
#define KK        16
#define T         64          // batch rows per block; lane carries a row PAIR (half2)
#define NTHREADS  1024
#define NWARPS    32
#define NBLOCKS   (B_TOTAL / T)          // 512
#define SPLIT     1536        // cols < SPLIT live in SMEM; cols >= SPLIT in global scratch
#define NCOLS_ALL 1920        // 128 + 7*256 (layer-7 out never re-gathered)
#define TBL       (NLAYERS * WID * KK)   // 32768 table entries

// SMEM layout (dynamic, 230,400 B total):
//   [0      , 196608) s_hist  : __half2 [1536][32]   (history, transposed, row pairs)
//   [196608 , 212992) s_tidx  : int     [256*16]     (pre-scaled byte offsets, idx*128)
//   [212992 , 229376) s_twt   : uint    [256*16]     (half2-broadcast weights)
//   [229376 , 230400) s_tbias : float   [256]        (fp32 biases)
#define OFF_TIDX  196608
#define OFF_TWT   212992
#define OFF_TBIAS 229376
#define SMEM_BYTES 230400

// Global scratch for evicted history cols [1536, 1920): [block][col'][32 pairs]
#define SC_COLS (NCOLS_ALL - SPLIT)      // 384
__device__ __half2      g_scratch[(size_t)NBLOCKS * SC_COLS * (T / 2)];
// Preprocessed tables (built by prep_kernel each replay)
__device__ unsigned int g_wh2 [TBL];     // weight as half2 broadcast (lo==hi)
__device__ int          g_idxb[TBL];     // edge_idx * 128 (byte offset into history)

extern __shared__ unsigned char smem_raw[];

__device__ __forceinline__ void cp16(unsigned int saddr, const void* gptr) {
    asm volatile("cp.async.cg.shared.global [%0], [%1], 16;\n"
                 :: "r"(saddr), "l"(gptr));
}

__device__ __forceinline__ __half2 u2h2(unsigned int u) {
    __half2 h;
    *(unsigned int*)&h = u;
    return h;
}

__device__ __forceinline__ float2 sigmoid2(float2 pre) {
    float2 s;
    s.x = __fdividef(1.0f, 1.0f + __expf(-pre.x));
    s.y = __fdividef(1.0f, 1.0f + __expf(-pre.y));
    return s;
}

// ---- prep: broadcast-pack weights to half2, pre-scale indices to byte offsets ----
__global__ void prep_kernel(const float* __restrict__ weights,
                            const int*   __restrict__ edge_idx) {
    int i = blockIdx.x * blockDim.x + threadIdx.x;   // exactly TBL threads
    __half  h  = __float2half(weights[i]);
    __half2 h2 = __half2half2(h);
    g_wh2 [i] = *(unsigned int*)&h2;
    g_idxb[i] = edge_idx[i] << 7;                    // *128 bytes per history col
}

// 16-edge dot, all offsets < SPLIT*128 guaranteed (layers 0..5)
__device__ __forceinline__ float2 pre_smem(const char* __restrict__ hlane,
                                           const int4* __restrict__ si4,
                                           const uint4* __restrict__ sw4,
                                           float bias, int w) {
    __half2 acc0 = __float2half2_rn(0.0f), acc1 = acc0, acc2 = acc0, acc3 = acc0;
    #pragma unroll
    for (int g = 0; g < 4; ++g) {
        int4  iv = si4[w * 4 + g];
        uint4 wv = sw4[w * 4 + g];
        __half2 a = (g & 1) ? acc2 : acc0;
        __half2 b = (g & 1) ? acc3 : acc1;
        a = __hfma2(*(const __half2*)(hlane + iv.x), u2h2(wv.x), a);
        b = __hfma2(*(const __half2*)(hlane + iv.y), u2h2(wv.y), b);
        a = __hfma2(*(const __half2*)(hlane + iv.z), u2h2(wv.z), a);
        b = __hfma2(*(const __half2*)(hlane + iv.w), u2h2(wv.w), b);
        if (g & 1) { acc2 = a; acc3 = b; } else { acc0 = a; acc1 = b; }
    }
    float2 r0 = __half22float2(acc0);
    float2 r1 = __half22float2(acc1);
    float2 r2 = __half22float2(acc2);
    float2 r3 = __half22float2(acc3);
    return make_float2(bias + (r0.x + r1.x) + (r2.x + r3.x),
                       bias + (r0.y + r1.y) + (r2.y + r3.y));
}

// layers 6,7: offsets may reach scratch -> branchless pointer select
__device__ __forceinline__ float2 pre_mixed(const char* __restrict__ hlane,
                                            const char* __restrict__ glane,
                                            const int4* __restrict__ si4,
                                            const uint4* __restrict__ sw4,
                                            float bias, int w) {
    const int LIM = SPLIT * 128;
    __half2 acc0 = __float2half2_rn(0.0f), acc1 = acc0, acc2 = acc0, acc3 = acc0;
    #pragma unroll
    for (int g = 0; g < 4; ++g) {
        int4  iv = si4[w * 4 + g];
        uint4 wv = sw4[w * 4 + g];
        const char* px = ((iv.x < LIM) ? hlane : glane) + iv.x;
        const char* py = ((iv.y < LIM) ? hlane : glane) + iv.y;
        const char* pz = ((iv.z < LIM) ? hlane : glane) + iv.z;
        const char* pw = ((iv.w < LIM) ? hlane : glane) + iv.w;
        __half2 a = (g & 1) ? acc2 : acc0;
        __half2 b = (g & 1) ? acc3 : acc1;
        a = __hfma2(*(const __half2*)px, u2h2(wv.x), a);
        b = __hfma2(*(const __half2*)py, u2h2(wv.y), b);
        a = __hfma2(*(const __half2*)pz, u2h2(wv.z), a);
        b = __hfma2(*(const __half2*)pw, u2h2(wv.w), b);
        if (g & 1) { acc2 = a; acc3 = b; } else { acc0 = a; acc1 = b; }
    }
    float2 r0 = __half22float2(acc0);
    float2 r1 = __half22float2(acc1);
    float2 r2 = __half22float2(acc2);
    float2 r3 = __half22float2(acc3);
    return make_float2(bias + (r0.x + r1.x) + (r2.x + r3.x),
                       bias + (r0.y + r1.y) + (r2.y + r3.y));
}

__global__ __launch_bounds__(NTHREADS, 1)
void ffn_edge_kernel(const float* __restrict__ inputs,    // [B, 128]
                     const float* __restrict__ biases,    // [L, W]
                     float*       __restrict__ out)       // [B, W]
{
    __half2* s_h2   = (__half2*)smem_raw;
    const int4*  si4 = (const int4*) (smem_raw + OFF_TIDX);
    const uint4* sw4 = (const uint4*)(smem_raw + OFF_TWT);
    const float* sb  = (const float*)(smem_raw + OFF_TBIAS);

    unsigned int s_base = (unsigned int)__cvta_generic_to_shared(smem_raw);

    const int tid  = threadIdx.x;
    const int lane = tid & 31;
    const int wid  = tid >> 5;
    const int row0 = blockIdx.x * T;

    __half2* gblk = g_scratch + (size_t)blockIdx.x * (SC_COLS * (T / 2));
    // per-lane base pointers (generic space); offsets from tables are bytes
    const char* hlane = (const char*)s_h2 + lane * 4;
    const char* glane = (const char*)gblk + lane * 4 - SPLIT * 128;

    // ---- Kick off layer-0 table prefetch (overlaps input staging) ----
    {
        cp16(s_base + OFF_TIDX + tid * 16, (const char*)g_idxb + tid * 16);
        cp16(s_base + OFF_TWT  + tid * 16, (const char*)g_wh2  + tid * 16);
        if (tid < 64) cp16(s_base + OFF_TBIAS + tid * 16, (const char*)biases + tid * 16);
        asm volatile("cp.async.commit_group;\n");
    }

    // ---- Stage input [64][128] fp32 coalesced into pad-132 buffer.
    // Overlays hist bytes [16384, 50176) = cols 128..391 (not yet written).
    float* s_stage = (float*)(smem_raw + 16384);
    {
        const float4* in4 = (const float4*)(inputs + (size_t)row0 * N_IN);
        #pragma unroll 1
        for (int i = tid; i < T * (N_IN / 4); i += NTHREADS) {
            int r  = i >> 5;            // 32 float4 per row
            int c4 = i & 31;
            float4 v = in4[i];
            float* dst = s_stage + r * 132 + c4 * 4;
            dst[0] = v.x; dst[1] = v.y; dst[2] = v.z; dst[3] = v.w;
        }
    }
    __syncthreads();
    // ---- Transpose-convert input into s_h2[col][pair]: lo = row 2p, hi = row 2p+1
    #pragma unroll 1
    for (int i = tid; i < N_IN * 32; i += NTHREADS) {
        int col = i >> 5;
        int p   = i & 31;
        float lo = s_stage[(2 * p)     * 132 + col];
        float hi = s_stage[(2 * p + 1) * 132 + col];
        s_h2[col * 32 + p] = __floats2half2_rn(lo, hi);
    }

    // ---- 8 layers; tables single-buffered in SMEM ----
    int ncols = N_IN;
    #pragma unroll 1
    for (int l = 0; l < NLAYERS; ++l) {
        asm volatile("cp.async.wait_group 0;\n");
        __syncthreads();   // tables visible + (l==0: input transposed) + hist stable

        if (l < 6) {
            // pure-SMEM gathers (cols < 1408 < SPLIT)
            #pragma unroll 1
            for (int w = wid; w < WID; w += NWARPS) {
                float2 pre = pre_smem(hlane, si4, sw4, sb[w], w);
                float2 sg  = sigmoid2(pre);
                __half2 h  = __floats2half2_rn(sg.x, sg.y);
                int col = ncols + w;
                if (col < SPLIT) s_h2[col * 32 + lane] = h;
                else             gblk[(col - SPLIT) * 32 + lane] = h;
            }
        } else if (l == 6) {
            // mixed gathers; output (cols 1664..1919) all to scratch
            #pragma unroll 1
            for (int w = wid; w < WID; w += NWARPS) {
                float2 pre = pre_mixed(hlane, glane, si4, sw4, sb[w], w);
                float2 sg  = sigmoid2(pre);
                gblk[(ncols + w - SPLIT) * 32 + lane] = __floats2half2_rn(sg.x, sg.y);
            }
        } else {
            // layer 7: mixed gathers; fp32 result straight to GMEM
            float* og = out + ((size_t)row0 + 2 * lane) * WID;
            #pragma unroll 1
            for (int w = wid; w < WID; w += NWARPS) {
                float2 pre = pre_mixed(hlane, glane, si4, sw4, sb[w], w);
                float2 sg  = sigmoid2(pre);
                og[w]       = sg.x;   // row 2*lane
                og[w + WID] = sg.y;   // row 2*lane + 1
            }
        }
        ncols += WID;

        if (l < NLAYERS - 1) {
            __syncthreads();   // everyone done reading this layer's tables
            const char* gi = (const char*)(g_idxb + (size_t)(l + 1) * WID * KK);
            const char* gw = (const char*)(g_wh2  + (size_t)(l + 1) * WID * KK);
            cp16(s_base + OFF_TIDX + tid * 16, gi + tid * 16);
            cp16(s_base + OFF_TWT  + tid * 16, gw + tid * 16);
            if (tid < 64)
                cp16(s_base + OFF_TBIAS + tid * 16,
                     (const char*)(biases + (size_t)(l + 1) * WID) + tid * 16);
            asm volatile("cp.async.commit_group;\n");
        }
    }
}

extern "C" void kernel_launch(void* const* d_in, const int* in_sizes, int n_in,
                              void* d_out, int out_size)
{
    (void)in_sizes; (void)n_in; (void)out_size;
    const float* inputs   = (const float*)d_in[0];
    const float* weights  = (const float*)d_in[1];
    const float* biases   = (const float*)d_in[2];
    const int*   edge_idx = (const int*)  d_in[3];
    float*       out      = (float*)d_out;

    cudaFuncSetAttribute(ffn_edge_kernel,
                         cudaFuncAttributeMaxDynamicSharedMemorySize, SMEM_BYTES);

    prep_kernel<<<TBL / 256, 256>>>(weights, edge_idx);

    dim3 grid(NBLOCKS);        // 512 blocks of 64 rows
    dim3 block(NTHREADS);
    ffn_edge_kernel<<<grid, block, SMEM_BYTES>>>(inputs, biases, out);
}